// round 11
// baseline (speedup 1.0000x reference)
#include <cuda_runtime.h>

// ---------------------------------------------------------------------------
// GCN_84559316124289 — collapsed graph + f32x2 FMA, 8-warps/SMSP everywhere.
//   P1 = pool(lrelu(conv1(x)+b1))
//   H2 = pool(lrelu(12*conv2w(P1) + 4*b2))
//   H3 = pool(lrelu(conv3(H2)+b3));  out[b] = wc . mean(H3) + bc
//
// 1x1-pooled tile per thread (2x2 conv px, 4x4 patch), ky-pipelined so only
// ~2 patch rows are live -> <=64 regs/thread:
//   k1: 512 thr, 2 blocks/SM;  k2/k3: 1024 thr, 1 block/SM (8 warps/SMSP).
// Weights in smem as [ci][k][co] (padded stride) -> broadcast LDS.128/LDS.64.
// ---------------------------------------------------------------------------

typedef unsigned long long ull;

__device__ __forceinline__ ull dup2(float x) {
    ull r; asm("mov.b64 %0, {%1, %1};" : "=l"(r) : "f"(x)); return r;
}
__device__ __forceinline__ void ffma2(ull& d, ull a, ull b) {
    asm("fma.rn.f32x2 %0, %1, %2, %0;" : "+l"(d) : "l"(a), "l"(b));
}
__device__ __forceinline__ void unpk(float& lo, float& hi, ull v) {
    asm("mov.b64 {%0, %1}, %2;" : "=f"(lo), "=f"(hi) : "l"(v));
}

#define LRELU(t) ((t) > 0.f ? (t) : 0.2f * (t))

__device__ float g_P1[32 * 32 * 32 * 32];   // [B, 32, 32, 32]
__device__ float g_H2[32 * 64 * 16 * 16];   // [B, 64, 16, 16]

// Load 4 consecutive floats of one patch row, duplicated into f32x2 regs.
#define LOADROW(DST, PTR)                                                      \
    { float2 u_ = *(const float2*)(PTR);                                       \
      float2 v_ = *(const float2*)((PTR) + 2);                                 \
      DST[0] = dup2(u_.x); DST[1] = dup2(u_.y);                                \
      DST[2] = dup2(v_.x); DST[3] = dup2(v_.y); }

// One kernel row (3 kx), 2 cout-pairs: broadcast LDS.128, 8 FFMA2 per kx.
#define KY2(RLO, RHI, KY, WP, WS)                                              \
    _Pragma("unroll")                                                          \
    for (int kx = 0; kx < 3; kx++) {                                           \
        ulonglong2 w = *(const ulonglong2*)((WP) + ((KY) * 3 + kx) * (WS));    \
        _Pragma("unroll")                                                      \
        for (int dx = 0; dx < 2; dx++) {                                       \
            ffma2(acc[0][dx],     RLO[dx + kx], w.x);                          \
            ffma2(acc[1][dx],     RLO[dx + kx], w.y);                          \
            ffma2(acc[0][2 + dx], RHI[dx + kx], w.x);                          \
            ffma2(acc[1][2 + dx], RHI[dx + kx], w.y);                          \
        }                                                                      \
    }

// One kernel row (3 kx), 1 cout-pair: broadcast LDS.64, 4 FFMA2 per kx.
#define KY1(RLO, RHI, KY, WP, WS)                                              \
    _Pragma("unroll")                                                          \
    for (int kx = 0; kx < 3; kx++) {                                           \
        ull w = *(const ull*)((WP) + ((KY) * 3 + kx) * (WS));                  \
        _Pragma("unroll")                                                      \
        for (int dx = 0; dx < 2; dx++) {                                       \
            ffma2(acc[dx],     RLO[dx + kx], w);                               \
            ffma2(acc[2 + dx], RHI[dx + kx], w);                               \
        }                                                                      \
    }

// Per-ci body, ky-pipelined (max ~3 rows live). acc[pair][dy*2+dx].
#define CI_2P(IB, WP, RS, WS)                                                  \
    {                                                                          \
        ull ra[4], rb[4], rc[4], rd[4];                                        \
        LOADROW(ra, (IB));                                                     \
        LOADROW(rb, (IB) + (RS));                                              \
        KY2(ra, rb, 0, WP, WS)                                                 \
        LOADROW(rc, (IB) + 2 * (RS));                                          \
        KY2(rb, rc, 1, WP, WS)                                                 \
        LOADROW(rd, (IB) + 3 * (RS));                                          \
        KY2(rc, rd, 2, WP, WS)                                                 \
    }

#define CI_1P(IB, WP, RS, WS)                                                  \
    {                                                                          \
        ull ra[4], rb[4], rc[4], rd[4];                                        \
        LOADROW(ra, (IB));                                                     \
        LOADROW(rb, (IB) + (RS));                                              \
        KY1(ra, rb, 0, WP, WS)                                                 \
        LOADROW(rc, (IB) + 2 * (RS));                                          \
        KY1(rb, rc, 1, WP, WS)                                                 \
        LOADROW(rd, (IB) + 3 * (RS));                                          \
        KY1(rc, rd, 2, WP, WS)                                                 \
    }

// ---------------------------------------------------------------------------
// Kernel 1: conv1 (4->32) + lrelu + pool.  grid(32,8) block 512, 2 blocks/SM.
// 4 couts per block; each thread 2 sequential 1x1-pooled tiles.
// s_in: 4ch x 66 x stride 68.  s_w: [ci*9+k]*4 + co(0..3).
// ---------------------------------------------------------------------------
__global__ void __launch_bounds__(512, 2)
k1_conv(const float* __restrict__ x,
        const float* __restrict__ w1,
        const float* __restrict__ b1,
        const float* __restrict__ bc,
        float* __restrict__ out) {
    extern __shared__ float sm[];
    float* s_in = sm;                  // 4*4488 = 17952
    float* s_w  = sm + 17952;          // 36*4 = 144

    const int b  = blockIdx.x;
    const int cg = blockIdx.y;         // couts [cg*4, cg*4+4)
    const int tid = threadIdx.x;

    if (cg == 0 && tid == 0) out[b] = bc[0];

    const float* xb = x + b * 16384;
    for (int j = tid; j < 4096; j += 512) {
        float4 v = *(const float4*)(xb + j * 4);
        int c = j >> 10, r = (j >> 4) & 63, x0 = (j & 15) * 4;
        float* d = s_in + c * 4488 + (r + 1) * 68 + x0 + 1;
        d[0] = v.x; d[1] = v.y; d[2] = v.z; d[3] = v.w;
    }
    for (int i = tid; i < 1056; i += 512) {
        int c = i / 264, t = i - c * 264;
        int row, col;
        if (t < 136) { row = (t >= 68) ? 65 : 0; col = t % 68; }
        else { int tt = t - 136; row = 1 + (tt >> 1); col = (tt & 1) ? 65 : 0; }
        s_in[c * 4488 + row * 68 + col] = 0.f;
    }
    if (tid < 144) {
        int co = tid / 36, r = tid - co * 36;
        s_w[r * 4 + co] = w1[cg * 144 + tid];
    }
    __syncthreads();

    #pragma unroll 1
    for (int p = 0; p < 2; p++) {
        int t = p * 512 + tid;
        int ph = t >> 5, pw = t & 31;

        ull acc[2][4];
        #pragma unroll
        for (int j = 0; j < 2; j++)
            #pragma unroll
            for (int q = 0; q < 4; q++) acc[j][q] = 0ull;

        #pragma unroll
        for (int ci = 0; ci < 4; ci++) {
            const float* ib = s_in + ci * 4488 + (2 * ph) * 68 + 2 * pw;
            const float* wp = s_w + ci * 36;
            CI_2P(ib, wp, 68, 4)
        }

        #pragma unroll
        for (int j = 0; j < 2; j++) {
            float v0[4], v1[4];
            #pragma unroll
            for (int q = 0; q < 4; q++) unpk(v0[q], v1[q], acc[j][q]);
            int co0 = cg * 4 + 2 * j;
            float bb0 = b1[co0], bb1 = b1[co0 + 1];
            float m0 = -1e30f, m1 = -1e30f;
            #pragma unroll
            for (int q = 0; q < 4; q++) {
                float t0 = v0[q] + bb0; t0 = LRELU(t0); m0 = fmaxf(m0, t0);
                float t1 = v1[q] + bb1; t1 = LRELU(t1); m1 = fmaxf(m1, t1);
            }
            g_P1[(b * 32 + co0) * 1024 + ph * 32 + pw] = m0;
            g_P1[(b * 32 + co0 + 1) * 1024 + ph * 32 + pw] = m1;
        }
    }
}

// ---------------------------------------------------------------------------
// Kernel 2: 12*conv2w (32->64) + 4*b2, lrelu, pool.  grid(32,4) block 1024.
// 4 subs (4 couts, warp-uniform) x 256 tiles (16x16 pooled).
// s_in: 32ch x 34 x stride 36.  s_w: [ci*9+k]*20 + co(0..15).
// ---------------------------------------------------------------------------
__global__ void __launch_bounds__(1024, 1)
k2_conv(const float* __restrict__ w2,
        const float* __restrict__ b2) {
    extern __shared__ float sm[];
    float* s_in = sm;                  // 32*1224 = 39168
    float* s_w  = sm + 39168;          // 288*20 = 5760

    const int b  = blockIdx.x;
    const int cg = blockIdx.y;
    const int tid = threadIdx.x;

    const float* pb = g_P1 + b * 32768;
    for (int j = tid; j < 8192; j += 1024) {
        float4 v = *(const float4*)(pb + j * 4);
        int c = j >> 8, r = (j >> 3) & 31, x0 = (j & 7) * 4;
        float* d = s_in + c * 1224 + (r + 1) * 36 + x0 + 1;
        d[0] = v.x; d[1] = v.y; d[2] = v.z; d[3] = v.w;
    }
    for (int i = tid; i < 32 * 136; i += 1024) {
        int c = i / 136, t = i - c * 136;
        int row, col;
        if (t < 72) { row = (t >= 36) ? 33 : 0; col = t % 36; }
        else { int tt = t - 72; row = 1 + (tt >> 1); col = (tt & 1) ? 33 : 0; }
        s_in[c * 1224 + row * 36 + col] = 0.f;
    }
    for (int i = tid * 4; i < 4608; i += 4096) {
        float4 wv = *(const float4*)(w2 + cg * 4608 + i);
        int co = i / 288, r = i - co * 288;
        s_w[(r + 0) * 20 + co] = wv.x;
        s_w[(r + 1) * 20 + co] = wv.y;
        s_w[(r + 2) * 20 + co] = wv.z;
        s_w[(r + 3) * 20 + co] = wv.w;
    }
    __syncthreads();

    const int sub = tid >> 8;          // 0..3 -> couts cg*16 + sub*4 ..
    const int t = tid & 255;
    const int ph = t >> 4, pw = t & 15;

    ull acc[2][4];
    #pragma unroll
    for (int j = 0; j < 2; j++)
        #pragma unroll
        for (int q = 0; q < 4; q++) acc[j][q] = 0ull;

    for (int ci = 0; ci < 32; ci++) {
        const float* ib = s_in + ci * 1224 + (2 * ph) * 36 + 2 * pw;
        const float* wp = s_w + ci * 180 + sub * 4;
        CI_2P(ib, wp, 36, 20)
    }

    #pragma unroll
    for (int j = 0; j < 2; j++) {
        float v0[4], v1[4];
        #pragma unroll
        for (int q = 0; q < 4; q++) unpk(v0[q], v1[q], acc[j][q]);
        int co0 = cg * 16 + sub * 4 + 2 * j;
        float bb0 = 4.f * b2[co0], bb1 = 4.f * b2[co0 + 1];
        float m0 = -1e30f, m1 = -1e30f;
        #pragma unroll
        for (int q = 0; q < 4; q++) {
            float t0 = fmaf(12.f, v0[q], bb0); t0 = LRELU(t0); m0 = fmaxf(m0, t0);
            float t1 = fmaf(12.f, v1[q], bb1); t1 = LRELU(t1); m1 = fmaxf(m1, t1);
        }
        g_H2[(b * 64 + co0) * 256 + ph * 16 + pw] = m0;
        g_H2[(b * 64 + co0 + 1) * 256 + ph * 16 + pw] = m1;
    }
}

// ---------------------------------------------------------------------------
// Kernel 3: conv3 (64->128) + lrelu + pool + mean + dot(wc).  grid(32,4), 1024.
// 16 subs (2 couts, warp-uniform) x 64 tiles (8x8 pooled).
// s_in: 64ch x 18 x stride 20.  s_w: [ci*9+k]*36 + co(0..31).
// ---------------------------------------------------------------------------
__global__ void __launch_bounds__(1024, 1)
k3_conv(const float* __restrict__ w3,
        const float* __restrict__ b3,
        const float* __restrict__ wc,
        float* __restrict__ out) {
    extern __shared__ float sm[];
    float* s_in  = sm;                 // 64*360 = 23040
    float* s_w   = sm + 23040;         // 576*36 = 20736
    float* s_red = s_w + 20736;        // 32*65 = 2080

    const int b  = blockIdx.x;
    const int cg = blockIdx.y;
    const int tid = threadIdx.x;

    const float* hb = g_H2 + b * 16384;
    for (int j = tid; j < 4096; j += 1024) {
        float4 v = *(const float4*)(hb + j * 4);
        int c = j >> 6, r = (j >> 2) & 15, x0 = (j & 3) * 4;
        float* d = s_in + c * 360 + (r + 1) * 20 + x0 + 1;
        d[0] = v.x; d[1] = v.y; d[2] = v.z; d[3] = v.w;
    }
    for (int i = tid; i < 64 * 72; i += 1024) {
        int c = i / 72, t = i - c * 72;
        int row, col;
        if (t < 40) { row = (t >= 20) ? 17 : 0; col = t % 20; }
        else { int tt = t - 40; row = 1 + (tt >> 1); col = (tt & 1) ? 17 : 0; }
        s_in[c * 360 + row * 20 + col] = 0.f;
    }
    for (int i = tid * 4; i < 18432; i += 4096) {
        float4 wv = *(const float4*)(w3 + cg * 18432 + i);
        int co = i / 576, r = i - co * 576;
        s_w[(r + 0) * 36 + co] = wv.x;
        s_w[(r + 1) * 36 + co] = wv.y;
        s_w[(r + 2) * 36 + co] = wv.z;
        s_w[(r + 3) * 36 + co] = wv.w;
    }
    __syncthreads();

    const int sub = tid >> 6;          // 0..15 -> couts sub*2, sub*2+1
    const int t = tid & 63;
    const int ph = t >> 3, pw = t & 7;

    ull acc[4];
    #pragma unroll
    for (int q = 0; q < 4; q++) acc[q] = 0ull;

    for (int ci = 0; ci < 64; ci++) {
        const float* ib = s_in + ci * 360 + (2 * ph) * 20 + 2 * pw;
        const float* wp = s_w + ci * 324 + sub * 2;
        CI_1P(ib, wp, 20, 36)
    }

    {
        float v0[4], v1[4];
        #pragma unroll
        for (int q = 0; q < 4; q++) unpk(v0[q], v1[q], acc[q]);
        int lco0 = sub * 2;
        float bb0 = b3[cg * 32 + lco0], bb1 = b3[cg * 32 + lco0 + 1];
        float m0 = -1e30f, m1 = -1e30f;
        #pragma unroll
        for (int q = 0; q < 4; q++) {
            float t0 = v0[q] + bb0; t0 = LRELU(t0); m0 = fmaxf(m0, t0);
            float t1 = v1[q] + bb1; t1 = LRELU(t1); m1 = fmaxf(m1, t1);
        }
        s_red[lco0 * 65 + t] = m0;
        s_red[(lco0 + 1) * 65 + t] = m1;
    }
    __syncthreads();

    if (tid < 32) {
        float s = 0.f;
        #pragma unroll 8
        for (int p2 = 0; p2 < 64; p2++) s += s_red[tid * 65 + p2];
        float part = wc[cg * 32 + tid] * s * (1.0f / 64.0f);
        #pragma unroll
        for (int off = 16; off; off >>= 1)
            part += __shfl_down_sync(0xffffffffu, part, off);
        if (tid == 0) atomicAdd(&out[b], part);
    }
}

extern "C" void kernel_launch(void* const* d_in, const int* in_sizes, int n_in,
                              void* d_out, int out_size) {
    const float* x  = (const float*)d_in[0];
    const float* w1 = (const float*)d_in[1];
    const float* b1 = (const float*)d_in[2];
    const float* w2 = (const float*)d_in[3];
    const float* b2 = (const float*)d_in[4];
    const float* w3 = (const float*)d_in[5];
    const float* b3 = (const float*)d_in[6];
    const float* wc = (const float*)d_in[7];
    const float* bc = (const float*)d_in[8];
    float* out = (float*)d_out;

    const size_t sm1 = (17952 + 144) * sizeof(float);           //  72 KB
    const size_t sm2 = (39168 + 5760) * sizeof(float);          // 180 KB
    const size_t sm3 = (23040 + 20736 + 2080) * sizeof(float);  // 183 KB

    cudaFuncSetAttribute(k1_conv, cudaFuncAttributeMaxDynamicSharedMemorySize, (int)sm1);
    cudaFuncSetAttribute(k2_conv, cudaFuncAttributeMaxDynamicSharedMemorySize, (int)sm2);
    cudaFuncSetAttribute(k3_conv, cudaFuncAttributeMaxDynamicSharedMemorySize, (int)sm3);

    k1_conv<<<dim3(32, 8), 512, sm1>>>(x, w1, b1, bc, out);
    k2_conv<<<dim3(32, 4), 1024, sm2>>>(w2, b2);
    k3_conv<<<dim3(32, 4), 1024, sm3>>>(w3, b3, wc, out);
}

// round 12
// speedup vs baseline: 1.3846x; 1.3846x over previous
#include <cuda_runtime.h>

// ---------------------------------------------------------------------------
// GCN_84559316124289 — collapsed graph + f32x2 FMA (R7 inner loop) with:
//   k1: row-sliced blocks (no staging duplication, 3 blocks/SM)
//   k2: unchanged from R7 (best known)
//   k3: ci-split across 2 thread-halves -> 4 warps/SMSP, packed-add combine
//
//   P1 = pool(lrelu(conv1(x)+b1))
//   H2 = pool(lrelu(12*conv2w(P1) + 4*b2))
//   H3 = pool(lrelu(conv3(H2)+b3));  out[b] = wc . mean(H3) + bc
// ---------------------------------------------------------------------------

typedef unsigned long long ull;

__device__ __forceinline__ ull dup2(float x) {
    ull r; asm("mov.b64 %0, {%1, %1};" : "=l"(r) : "f"(x)); return r;
}
__device__ __forceinline__ void ffma2(ull& d, ull a, ull b) {
    asm("fma.rn.f32x2 %0, %1, %2, %0;" : "+l"(d) : "l"(a), "l"(b));
}
__device__ __forceinline__ ull addf2(ull a, ull b) {
    ull r; asm("add.rn.f32x2 %0, %1, %2;" : "=l"(r) : "l"(a), "l"(b)); return r;
}
__device__ __forceinline__ void unpk(float& lo, float& hi, ull v) {
    asm("mov.b64 {%0, %1}, %2;" : "=f"(lo), "=f"(hi) : "l"(v));
}

#define LRELU(t) ((t) > 0.f ? (t) : 0.2f * (t))

__device__ float g_P1[32 * 32 * 32 * 32];   // [B, 32, 32, 32]
__device__ float g_H2[32 * 64 * 16 * 16];   // [B, 64, 16, 16]

// Load 4x6 patch and duplicate each value into an f32x2 register.
#define LOAD_PATCH(IB, RS)                                                     \
    ull pd[4][6];                                                              \
    _Pragma("unroll")                                                          \
    for (int r = 0; r < 4; r++) {                                              \
        float4 a4 = *(const float4*)((IB) + r * (RS));                         \
        float2 b2v = *(const float2*)((IB) + r * (RS) + 4);                    \
        pd[r][0] = dup2(a4.x);  pd[r][1] = dup2(a4.y);                         \
        pd[r][2] = dup2(a4.z);  pd[r][3] = dup2(a4.w);                         \
        pd[r][4] = dup2(b2v.x); pd[r][5] = dup2(b2v.y);                        \
    }

// Two cout-pairs (4 couts): 9 broadcast LDS.128, 16 FFMA2 / k.
#define CONV_CI_2P(IB, WP, RS, WS)                                             \
    {                                                                          \
        LOAD_PATCH(IB, RS)                                                     \
        _Pragma("unroll")                                                      \
        for (int k = 0; k < 9; k++) {                                          \
            ulonglong2 w = *(const ulonglong2*)((WP) + k * (WS));              \
            int ky = k / 3, kx = k - ky * 3;                                   \
            _Pragma("unroll")                                                  \
            for (int dy = 0; dy < 2; dy++)                                     \
                _Pragma("unroll")                                              \
                for (int dx = 0; dx < 4; dx++) {                               \
                    ull pv = pd[dy + ky][dx + kx];                             \
                    int q = dy * 4 + dx;                                       \
                    ffma2(acc[0][q], pv, w.x);                                 \
                    ffma2(acc[1][q], pv, w.y);                                 \
                }                                                              \
        }                                                                      \
    }

// ---------------------------------------------------------------------------
// Kernel 1: conv1 (4->32) + lrelu + pool.  grid(32, 16 row-slices) block 256.
// Each block: 2 pooled rows x 32 pooled cols x ALL 32 couts.
// Stages only 6 input rows (4 conv + halo) per ch: s_in 4 x 6 x 68 = 1632.
// s_w: [g][ci*9+k][co0..3], g = cout-group.  8 groups x 32 tiles = 256 thr.
// ---------------------------------------------------------------------------
__global__ void __launch_bounds__(256, 3)
k1_conv(const float* __restrict__ x,
        const float* __restrict__ w1,
        const float* __restrict__ b1,
        const float* __restrict__ bc,
        float* __restrict__ out) {
    extern __shared__ float sm[];
    float* s_in = sm;                  // 4*6*68 = 1632
    float* s_w  = sm + 1632;           // 8*144 = 1152

    const int b  = blockIdx.x;
    const int ys = blockIdx.y;         // pooled rows [2*ys, 2*ys+2)
    const int tid = threadIdx.x;

    if (ys == 0 && tid == 0) out[b] = bc[0];

    const float* xb = x + b * 16384;
    const int row0 = 4 * ys - 1;       // first staged conv row
    for (int i = tid; i < 1632; i += 256) {
        int c = i / 408, r2 = i - c * 408;
        int row = r2 / 68, col = r2 - row * 68;
        int gy = row0 + row, gx = col - 1;
        float v = 0.f;
        if ((unsigned)gy < 64u && (unsigned)gx < 64u) v = xb[c * 4096 + gy * 64 + gx];
        s_in[i] = v;
    }
    for (int i = tid; i < 1152; i += 256) {
        int co = i / 36, r = i - co * 36;
        s_w[(co >> 2) * 144 + r * 4 + (co & 3)] = w1[i];
    }
    __syncthreads();

    const int g = tid >> 5;            // cout-group 0..7
    const int pos = tid & 31;
    const int ph = pos >> 4, pw = pos & 15;   // local pooled row, col-pair

    ull acc[2][8];
    #pragma unroll
    for (int j = 0; j < 2; j++)
        #pragma unroll
        for (int q = 0; q < 8; q++) acc[j][q] = 0ull;

    #pragma unroll
    for (int ci = 0; ci < 4; ci++) {
        const float* ib = s_in + ci * 408 + (2 * ph) * 68 + 4 * pw;
        const float* wp = s_w + g * 144 + ci * 36;
        CONV_CI_2P(ib, wp, 68, 4)
    }

    #pragma unroll
    for (int j = 0; j < 2; j++) {
        float v0[8], v1[8];
        #pragma unroll
        for (int q = 0; q < 8; q++) unpk(v0[q], v1[q], acc[j][q]);
        int co0 = g * 4 + 2 * j;
        float bb0 = b1[co0], bb1 = b1[co0 + 1];
        float m0[2], m1[2];
        #pragma unroll
        for (int c2 = 0; c2 < 2; c2++) {
            float a0 = -1e30f, a1 = -1e30f;
            #pragma unroll
            for (int dy = 0; dy < 2; dy++)
                #pragma unroll
                for (int dx = 0; dx < 2; dx++) {
                    int q = dy * 4 + 2 * c2 + dx;
                    float t0 = v0[q] + bb0; t0 = LRELU(t0); a0 = fmaxf(a0, t0);
                    float t1 = v1[q] + bb1; t1 = LRELU(t1); a1 = fmaxf(a1, t1);
                }
            m0[c2] = a0; m1[c2] = a1;
        }
        int py = 2 * ys + ph;
        *(float2*)(g_P1 + (b * 32 + co0) * 1024 + py * 32 + 2 * pw) =
            make_float2(m0[0], m0[1]);
        *(float2*)(g_P1 + (b * 32 + co0 + 1) * 1024 + py * 32 + 2 * pw) =
            make_float2(m1[0], m1[1]);
    }
}

// ---------------------------------------------------------------------------
// Kernel 2 (unchanged from R7): 12*conv2w (32->64) + 4*b2, lrelu, pool.
// grid(32,4) block 512.  4 subs (4 couts) x 128 tiles; warp-uniform sub.
// s_in: 32ch x 34 x stride 36.  s_w: [ci*9+k]*20 + co(0..15).
// ---------------------------------------------------------------------------
__global__ void __launch_bounds__(512, 1)
k2_conv(const float* __restrict__ w2,
        const float* __restrict__ b2) {
    extern __shared__ float sm[];
    float* s_in = sm;                  // 32*1224 = 39168
    float* s_w  = sm + 39168;          // 288*20 = 5760

    const int b  = blockIdx.x;
    const int cg = blockIdx.y;
    const int tid = threadIdx.x;

    const float* pb = g_P1 + b * 32768;
    for (int j = tid; j < 8192; j += 512) {
        float4 v = *(const float4*)(pb + j * 4);
        int c = j >> 8, r = (j >> 3) & 31, x0 = (j & 7) * 4;
        float* d = s_in + c * 1224 + (r + 1) * 36 + x0 + 1;
        d[0] = v.x; d[1] = v.y; d[2] = v.z; d[3] = v.w;
    }
    for (int i = tid; i < 32 * 136; i += 512) {
        int c = i / 136, t = i - c * 136;
        int row, col;
        if (t < 72) { row = (t >= 36) ? 33 : 0; col = t % 36; }
        else { int tt = t - 72; row = 1 + (tt >> 1); col = (tt & 1) ? 33 : 0; }
        s_in[c * 1224 + row * 36 + col] = 0.f;
    }
    for (int i = tid * 4; i < 4608; i += 2048) {
        float4 wv = *(const float4*)(w2 + cg * 4608 + i);
        int co = i / 288, r = i - co * 288;
        s_w[(r + 0) * 20 + co] = wv.x;
        s_w[(r + 1) * 20 + co] = wv.y;
        s_w[(r + 2) * 20 + co] = wv.z;
        s_w[(r + 3) * 20 + co] = wv.w;
    }
    __syncthreads();

    const int sub = tid >> 7;
    const int pxg = tid & 127;
    const int gh = pxg >> 3, gw = pxg & 7;

    ull acc[2][8];
    #pragma unroll
    for (int j = 0; j < 2; j++)
        #pragma unroll
        for (int q = 0; q < 8; q++) acc[j][q] = 0ull;

    for (int ci = 0; ci < 32; ci++) {
        const float* ib = s_in + ci * 1224 + (2 * gh) * 36 + 4 * gw;
        const float* wp = s_w + ci * 180 + sub * 4;
        CONV_CI_2P(ib, wp, 36, 20)
    }

    #pragma unroll
    for (int j = 0; j < 2; j++) {
        float v0[8], v1[8];
        #pragma unroll
        for (int q = 0; q < 8; q++) unpk(v0[q], v1[q], acc[j][q]);
        int co0 = cg * 16 + sub * 4 + 2 * j;
        float bb0 = 4.f * b2[co0], bb1 = 4.f * b2[co0 + 1];
        float m0[2], m1[2];
        #pragma unroll
        for (int c2 = 0; c2 < 2; c2++) {
            float a0 = -1e30f, a1 = -1e30f;
            #pragma unroll
            for (int dy = 0; dy < 2; dy++)
                #pragma unroll
                for (int dx = 0; dx < 2; dx++) {
                    int q = dy * 4 + 2 * c2 + dx;
                    float t0 = fmaf(12.f, v0[q], bb0); t0 = LRELU(t0); a0 = fmaxf(a0, t0);
                    float t1 = fmaf(12.f, v1[q], bb1); t1 = LRELU(t1); a1 = fmaxf(a1, t1);
                }
            m0[c2] = a0; m1[c2] = a1;
        }
        *(float2*)(g_H2 + (b * 64 + co0) * 256 + gh * 16 + 2 * gw) =
            make_float2(m0[0], m0[1]);
        *(float2*)(g_H2 + (b * 64 + co0 + 1) * 256 + gh * 16 + 2 * gw) =
            make_float2(m1[0], m1[1]);
    }
}

// ---------------------------------------------------------------------------
// Kernel 3: conv3 (64->128) + lrelu + pool + mean + dot(wc).  grid(32,4), 512.
// ci-split: half h = tid>>8 does ci [h*32, h*32+32); workers (tid&255) are
// R7's 8 subs (4 couts) x 32 tiles.  h=1 stores partial accs to smem
// (stride-17 ull, conflict-free); h=0 combines with packed adds + epilogue.
// ---------------------------------------------------------------------------
__global__ void __launch_bounds__(512, 1)
k3_conv(const float* __restrict__ w3,
        const float* __restrict__ b3,
        const float* __restrict__ wc,
        float* __restrict__ out) {
    extern __shared__ float sm[];
    float* s_in  = sm;                 // 64*360 = 23040
    float* s_w   = sm + 23040;         // 576*36 = 20736
    ull*   s_part = (ull*)(sm + 43776);// 256*17 ull = 8704 floats
    float* s_red = sm + 52480;         // 32*65 = 2080

    const int b  = blockIdx.x;
    const int cg = blockIdx.y;
    const int tid = threadIdx.x;

    const float* hb = g_H2 + b * 16384;
    for (int j = tid; j < 4096; j += 512) {
        float4 v = *(const float4*)(hb + j * 4);
        int c = j >> 6, r = (j >> 2) & 15, x0 = (j & 3) * 4;
        float* d = s_in + c * 360 + (r + 1) * 20 + x0 + 1;
        d[0] = v.x; d[1] = v.y; d[2] = v.z; d[3] = v.w;
    }
    for (int i = tid; i < 64 * 72; i += 512) {
        int c = i / 72, t = i - c * 72;
        int row, col;
        if (t < 40) { row = (t >= 20) ? 17 : 0; col = t % 20; }
        else { int tt = t - 40; row = 1 + (tt >> 1); col = (tt & 1) ? 17 : 0; }
        s_in[c * 360 + row * 20 + col] = 0.f;
    }
    for (int i = tid * 4; i < 18432; i += 2048) {
        float4 wv = *(const float4*)(w3 + cg * 18432 + i);
        int co = i / 576, r = i - co * 576;
        s_w[(r + 0) * 36 + co] = wv.x;
        s_w[(r + 1) * 36 + co] = wv.y;
        s_w[(r + 2) * 36 + co] = wv.z;
        s_w[(r + 3) * 36 + co] = wv.w;
    }
    __syncthreads();

    const int h  = tid >> 8;           // ci half
    const int wt = tid & 255;          // worker id
    const int sub = wt >> 5;           // 0..7 -> couts sub*4..+3
    const int pxg = wt & 31;
    const int gh = pxg >> 2, gw = pxg & 3;

    ull acc[2][8];
    #pragma unroll
    for (int j = 0; j < 2; j++)
        #pragma unroll
        for (int q = 0; q < 8; q++) acc[j][q] = 0ull;

    const int cib = h * 32;
    for (int ci = cib; ci < cib + 32; ci++) {
        const float* ib = s_in + ci * 360 + (2 * gh) * 20 + 4 * gw;
        const float* wp = s_w + ci * 324 + sub * 4;
        CONV_CI_2P(ib, wp, 20, 36)
    }

    ull* sp = s_part + wt * 17;
    if (h) {
        #pragma unroll
        for (int j = 0; j < 2; j++)
            #pragma unroll
            for (int q = 0; q < 8; q++) sp[j * 8 + q] = acc[j][q];
    }
    __syncthreads();

    if (!h) {
        #pragma unroll
        for (int j = 0; j < 2; j++)
            #pragma unroll
            for (int q = 0; q < 8; q++) acc[j][q] = addf2(acc[j][q], sp[j * 8 + q]);

        #pragma unroll
        for (int j = 0; j < 2; j++) {
            float v0[8], v1[8];
            #pragma unroll
            for (int q = 0; q < 8; q++) unpk(v0[q], v1[q], acc[j][q]);
            int lco0 = sub * 4 + 2 * j;
            float bb0 = b3[cg * 32 + lco0], bb1 = b3[cg * 32 + lco0 + 1];
            #pragma unroll
            for (int c2 = 0; c2 < 2; c2++) {
                float a0 = -1e30f, a1 = -1e30f;
                #pragma unroll
                for (int dy = 0; dy < 2; dy++)
                    #pragma unroll
                    for (int dx = 0; dx < 2; dx++) {
                        int q = dy * 4 + 2 * c2 + dx;
                        float t0 = v0[q] + bb0; t0 = LRELU(t0); a0 = fmaxf(a0, t0);
                        float t1 = v1[q] + bb1; t1 = LRELU(t1); a1 = fmaxf(a1, t1);
                    }
                int ppx = gh * 8 + 2 * gw + c2;
                s_red[lco0 * 65 + ppx] = a0;
                s_red[(lco0 + 1) * 65 + ppx] = a1;
            }
        }
    }
    __syncthreads();

    if (tid < 32) {
        float s = 0.f;
        #pragma unroll 8
        for (int p2 = 0; p2 < 64; p2++) s += s_red[tid * 65 + p2];
        float part = wc[cg * 32 + tid] * s * (1.0f / 64.0f);
        #pragma unroll
        for (int off = 16; off; off >>= 1)
            part += __shfl_down_sync(0xffffffffu, part, off);
        if (tid == 0) atomicAdd(&out[b], part);
    }
}

extern "C" void kernel_launch(void* const* d_in, const int* in_sizes, int n_in,
                              void* d_out, int out_size) {
    const float* x  = (const float*)d_in[0];
    const float* w1 = (const float*)d_in[1];
    const float* b1 = (const float*)d_in[2];
    const float* w2 = (const float*)d_in[3];
    const float* b2 = (const float*)d_in[4];
    const float* w3 = (const float*)d_in[5];
    const float* b3 = (const float*)d_in[6];
    const float* wc = (const float*)d_in[7];
    const float* bc = (const float*)d_in[8];
    float* out = (float*)d_out;

    const size_t sm1 = (1632 + 1152) * sizeof(float);           //  11 KB
    const size_t sm2 = (39168 + 5760) * sizeof(float);          // 180 KB
    const size_t sm3 = (52480 + 2080) * sizeof(float);          // 218 KB

    cudaFuncSetAttribute(k1_conv, cudaFuncAttributeMaxDynamicSharedMemorySize, (int)sm1);
    cudaFuncSetAttribute(k2_conv, cudaFuncAttributeMaxDynamicSharedMemorySize, (int)sm2);
    cudaFuncSetAttribute(k3_conv, cudaFuncAttributeMaxDynamicSharedMemorySize, (int)sm3);

    k1_conv<<<dim3(32, 16), 256, sm1>>>(x, w1, b1, bc, out);
    k2_conv<<<dim3(32, 4), 512, sm2>>>(w2, b2);
    k3_conv<<<dim3(32, 4), 512, sm3>>>(w3, b3, wc, out);
}

// round 15
// speedup vs baseline: 1.4174x; 1.0237x over previous
#include <cuda_runtime.h>

// ---------------------------------------------------------------------------
// GCN_84559316124289 — collapsed graph, conv1 FUSED into conv2 (2 kernels).
//
//   P1 = pool(lrelu(conv1(x)+b1))                      (strip, in smem only)
//   H2 = pool(lrelu(12*conv2w(P1) + 4*b2))             (k12_conv)
//   H3 = pool(lrelu(conv3(H2)+b3)); out = wc.mean+bc   (k3_conv, R11 ci-split)
//
// R13 bug fixed: w1 staging was `if (tid < 1152)` in a 512-thread block,
// leaving s_w1[512..1151] stale. Now a grid-stride loop.
// ---------------------------------------------------------------------------

typedef unsigned long long ull;

__device__ __forceinline__ ull dup2(float x) {
    ull r; asm("mov.b64 %0, {%1, %1};" : "=l"(r) : "f"(x)); return r;
}
__device__ __forceinline__ void ffma2(ull& d, ull a, ull b) {
    asm("fma.rn.f32x2 %0, %1, %2, %0;" : "+l"(d) : "l"(a), "l"(b));
}
__device__ __forceinline__ ull addf2(ull a, ull b) {
    ull r; asm("add.rn.f32x2 %0, %1, %2;" : "=l"(r) : "l"(a), "l"(b)); return r;
}
__device__ __forceinline__ void unpk(float& lo, float& hi, ull v) {
    asm("mov.b64 {%0, %1}, %2;" : "=f"(lo), "=f"(hi) : "l"(v));
}

#define LRELU(t) ((t) > 0.f ? (t) : 0.2f * (t))

__device__ float g_H2[32 * 64 * 16 * 16];   // [B, 64, 16, 16]

// Load 4x6 patch and duplicate each value into an f32x2 register.
#define LOAD_PATCH(IB, RS)                                                     \
    ull pd[4][6];                                                              \
    _Pragma("unroll")                                                          \
    for (int r = 0; r < 4; r++) {                                              \
        float4 a4 = *(const float4*)((IB) + r * (RS));                         \
        float2 b2v = *(const float2*)((IB) + r * (RS) + 4);                    \
        pd[r][0] = dup2(a4.x);  pd[r][1] = dup2(a4.y);                         \
        pd[r][2] = dup2(a4.z);  pd[r][3] = dup2(a4.w);                         \
        pd[r][4] = dup2(b2v.x); pd[r][5] = dup2(b2v.y);                        \
    }

// Two cout-pairs (4 couts): 9 broadcast LDS.128, 16 FFMA2 / k.
#define CONV_CI_2P(IB, WP, RS, WS)                                             \
    {                                                                          \
        LOAD_PATCH(IB, RS)                                                     \
        _Pragma("unroll")                                                      \
        for (int k = 0; k < 9; k++) {                                          \
            ulonglong2 w = *(const ulonglong2*)((WP) + k * (WS));              \
            int ky = k / 3, kx = k - ky * 3;                                   \
            _Pragma("unroll")                                                  \
            for (int dy = 0; dy < 2; dy++)                                     \
                _Pragma("unroll")                                              \
                for (int dx = 0; dx < 4; dx++) {                               \
                    ull pv = pd[dy + ky][dx + kx];                             \
                    int q = dy * 4 + dx;                                       \
                    ffma2(acc[0][q], pv, w.x);                                 \
                    ffma2(acc[1][q], pv, w.y);                                 \
                }                                                              \
        }                                                                      \
    }

// ---------------------------------------------------------------------------
// Fused conv1+conv2.  grid(32, 4 strips), block 512.
// smem: s_x 4x22x72=6336 | s_p1 32x10x36=11520 | s_w1 36x32=1152 | s_w2 288x68
// ---------------------------------------------------------------------------
__global__ void __launch_bounds__(512, 1)
k12_conv(const float* __restrict__ x,
         const float* __restrict__ w1,
         const float* __restrict__ b1,
         const float* __restrict__ w2,
         const float* __restrict__ b2,
         const float* __restrict__ bc,
         float* __restrict__ out) {
    extern __shared__ float sm[];
    float* s_x  = sm;                  // 6336
    float* s_p1 = sm + 6336;           // 11520
    float* s_w1 = sm + 17856;          // 1152
    float* s_w2 = sm + 19008;          // 19584  (total 38592 fl = 150.75 KB)

    const int b  = blockIdx.x;
    const int qy = blockIdx.y;         // strip: H2 rows [4*qy, 4*qy+4)
    const int tid = threadIdx.x;

    if (qy == 0 && tid == 0) out[b] = bc[0];

    // --- stage x strip: rows gxr = 16*qy-3 .. +18, cols gxc = -3 .. 68 ---
    const float* xb = x + b * 16384;
    for (int i = tid; i < 6336; i += 512) {
        int ch = i / 1584, rem = i - ch * 1584;
        int r = rem / 72, c = rem - r * 72;
        int gxr = 16 * qy - 3 + r, gxc = c - 3;
        float v = 0.f;
        if ((unsigned)gxr < 64u && (unsigned)gxc < 64u)
            v = xb[ch * 4096 + gxr * 64 + gxc];
        s_x[i] = v;
    }
    // --- stage w1: [ci*9+k]*32 + co  (FIXED: full grid-stride loop) ---
    for (int i = tid; i < 1152; i += 512) {
        int co = i / 36, r = i - co * 36;
        s_w1[r * 32 + co] = w1[i];
    }
    // --- stage w2 (all 64 couts): [ci*9+k]*68 + co ---
    for (int i = tid * 4; i < 18432; i += 2048) {
        float4 wv = *(const float4*)(w2 + i);
        int co = i / 288, r = i - co * 288;
        s_w2[(r + 0) * 68 + co] = wv.x;
        s_w2[(r + 1) * 68 + co] = wv.y;
        s_w2[(r + 2) * 68 + co] = wv.z;
        s_w2[(r + 3) * 68 + co] = wv.w;
    }
    __syncthreads();

    // --- conv1 phase: P1 strip rows gpy = 8*qy-1 .. +8 (10), cols -1..32 ---
    // unit = (g: 4-cout group 0..7) x (py 0..9) x (pxq 0..16)
    for (int u = tid; u < 1360; u += 512) {
        int g = u / 170, t = u - g * 170;
        int py = t / 17, pxq = t - py * 17;

        ull acc[2][8];
        #pragma unroll
        for (int j = 0; j < 2; j++)
            #pragma unroll
            for (int q = 0; q < 8; q++) acc[j][q] = 0ull;

        #pragma unroll
        for (int ci = 0; ci < 4; ci++) {
            const float* ib = s_x + ci * 1584 + (2 * py) * 72 + 4 * pxq;
            const float* wp = s_w1 + ci * 288 + g * 4;
            CONV_CI_2P(ib, wp, 72, 32)
        }

        int gpy = 8 * qy - 1 + py;
        bool rowok = (unsigned)gpy < 32u;
        #pragma unroll
        for (int j = 0; j < 2; j++) {
            float v0[8], v1[8];
            #pragma unroll
            for (int q = 0; q < 8; q++) unpk(v0[q], v1[q], acc[j][q]);
            int co0 = g * 4 + 2 * j;
            float bb0 = b1[co0], bb1 = b1[co0 + 1];
            #pragma unroll
            for (int c2 = 0; c2 < 2; c2++) {
                float a0 = -1e30f, a1 = -1e30f;
                #pragma unroll
                for (int dy = 0; dy < 2; dy++)
                    #pragma unroll
                    for (int dx = 0; dx < 2; dx++) {
                        int q = dy * 4 + 2 * c2 + dx;
                        float t0 = v0[q] + bb0; t0 = LRELU(t0); a0 = fmaxf(a0, t0);
                        float t1 = v1[q] + bb1; t1 = LRELU(t1); a1 = fmaxf(a1, t1);
                    }
                int gpx = 2 * pxq + c2 - 1;
                bool ok = rowok && ((unsigned)gpx < 32u);
                int base = py * 36 + 2 * pxq + c2;
                s_p1[co0 * 360 + base]       = ok ? a0 : 0.f;
                s_p1[(co0 + 1) * 360 + base] = ok ? a1 : 0.f;
            }
        }
    }
    __syncthreads();

    // --- conv2 phase (R7 layout): 16 subs (4 couts) x 32 tiles (4gh x 8gw) ---
    const int sub = tid >> 5;
    const int t2 = tid & 31;
    const int gh = t2 >> 3, gw = t2 & 7;

    ull acc[2][8];
    #pragma unroll
    for (int j = 0; j < 2; j++)
        #pragma unroll
        for (int q = 0; q < 8; q++) acc[j][q] = 0ull;

    for (int ci = 0; ci < 32; ci++) {
        const float* ib = s_p1 + ci * 360 + (2 * gh) * 36 + 4 * gw;
        const float* wp = s_w2 + ci * 612 + sub * 4;
        CONV_CI_2P(ib, wp, 36, 68)
    }

    #pragma unroll
    for (int j = 0; j < 2; j++) {
        float v0[8], v1[8];
        #pragma unroll
        for (int q = 0; q < 8; q++) unpk(v0[q], v1[q], acc[j][q]);
        int co0 = sub * 4 + 2 * j;
        float bb0 = 4.f * b2[co0], bb1 = 4.f * b2[co0 + 1];
        float m0[2], m1[2];
        #pragma unroll
        for (int c2 = 0; c2 < 2; c2++) {
            float a0 = -1e30f, a1 = -1e30f;
            #pragma unroll
            for (int dy = 0; dy < 2; dy++)
                #pragma unroll
                for (int dx = 0; dx < 2; dx++) {
                    int q = dy * 4 + 2 * c2 + dx;
                    float t0 = fmaf(12.f, v0[q], bb0); t0 = LRELU(t0); a0 = fmaxf(a0, t0);
                    float t1 = fmaf(12.f, v1[q], bb1); t1 = LRELU(t1); a1 = fmaxf(a1, t1);
                }
            m0[c2] = a0; m1[c2] = a1;
        }
        int row = 4 * qy + gh;
        *(float2*)(g_H2 + (b * 64 + co0) * 256 + row * 16 + 2 * gw) =
            make_float2(m0[0], m0[1]);
        *(float2*)(g_H2 + (b * 64 + co0 + 1) * 256 + row * 16 + 2 * gw) =
            make_float2(m1[0], m1[1]);
    }
}

// ---------------------------------------------------------------------------
// Kernel 3 (unchanged R11): conv3 (64->128) + lrelu + pool + mean + dot(wc).
// grid(32,4), 512 thr; ci-split halves, packed-add combine.
// ---------------------------------------------------------------------------
__global__ void __launch_bounds__(512, 1)
k3_conv(const float* __restrict__ w3,
        const float* __restrict__ b3,
        const float* __restrict__ wc,
        float* __restrict__ out) {
    extern __shared__ float sm[];
    float* s_in  = sm;                 // 64*360 = 23040
    float* s_w   = sm + 23040;         // 576*36 = 20736
    ull*   s_part = (ull*)(sm + 43776);// 256*17 ull
    float* s_red = sm + 52480;         // 32*65 = 2080

    const int b  = blockIdx.x;
    const int cg = blockIdx.y;
    const int tid = threadIdx.x;

    const float* hb = g_H2 + b * 16384;
    for (int j = tid; j < 4096; j += 512) {
        float4 v = *(const float4*)(hb + j * 4);
        int c = j >> 6, r = (j >> 2) & 15, x0 = (j & 3) * 4;
        float* d = s_in + c * 360 + (r + 1) * 20 + x0 + 1;
        d[0] = v.x; d[1] = v.y; d[2] = v.z; d[3] = v.w;
    }
    for (int i = tid; i < 64 * 72; i += 512) {
        int c = i / 72, t = i - c * 72;
        int row, col;
        if (t < 40) { row = (t >= 20) ? 17 : 0; col = t % 20; }
        else { int tt = t - 40; row = 1 + (tt >> 1); col = (tt & 1) ? 17 : 0; }
        s_in[c * 360 + row * 20 + col] = 0.f;
    }
    for (int i = tid * 4; i < 18432; i += 2048) {
        float4 wv = *(const float4*)(w3 + cg * 18432 + i);
        int co = i / 576, r = i - co * 576;
        s_w[(r + 0) * 36 + co] = wv.x;
        s_w[(r + 1) * 36 + co] = wv.y;
        s_w[(r + 2) * 36 + co] = wv.z;
        s_w[(r + 3) * 36 + co] = wv.w;
    }
    __syncthreads();

    const int h  = tid >> 8;
    const int wt = tid & 255;
    const int sub = wt >> 5;
    const int pxg = wt & 31;
    const int gh = pxg >> 2, gw = pxg & 3;

    ull acc[2][8];
    #pragma unroll
    for (int j = 0; j < 2; j++)
        #pragma unroll
        for (int q = 0; q < 8; q++) acc[j][q] = 0ull;

    const int cib = h * 32;
    for (int ci = cib; ci < cib + 32; ci++) {
        const float* ib = s_in + ci * 360 + (2 * gh) * 20 + 4 * gw;
        const float* wp = s_w + ci * 324 + sub * 4;
        CONV_CI_2P(ib, wp, 20, 36)
    }

    ull* sp = s_part + wt * 17;
    if (h) {
        #pragma unroll
        for (int j = 0; j < 2; j++)
            #pragma unroll
            for (int q = 0; q < 8; q++) sp[j * 8 + q] = acc[j][q];
    }
    __syncthreads();

    if (!h) {
        #pragma unroll
        for (int j = 0; j < 2; j++)
            #pragma unroll
            for (int q = 0; q < 8; q++) acc[j][q] = addf2(acc[j][q], sp[j * 8 + q]);

        #pragma unroll
        for (int j = 0; j < 2; j++) {
            float v0[8], v1[8];
            #pragma unroll
            for (int q = 0; q < 8; q++) unpk(v0[q], v1[q], acc[j][q]);
            int lco0 = sub * 4 + 2 * j;
            float bb0 = b3[cg * 32 + lco0], bb1 = b3[cg * 32 + lco0 + 1];
            #pragma unroll
            for (int c2 = 0; c2 < 2; c2++) {
                float a0 = -1e30f, a1 = -1e30f;
                #pragma unroll
                for (int dy = 0; dy < 2; dy++)
                    #pragma unroll
                    for (int dx = 0; dx < 2; dx++) {
                        int q = dy * 4 + 2 * c2 + dx;
                        float t0 = v0[q] + bb0; t0 = LRELU(t0); a0 = fmaxf(a0, t0);
                        float t1 = v1[q] + bb1; t1 = LRELU(t1); a1 = fmaxf(a1, t1);
                    }
                int ppx = gh * 8 + 2 * gw + c2;
                s_red[lco0 * 65 + ppx] = a0;
                s_red[(lco0 + 1) * 65 + ppx] = a1;
            }
        }
    }
    __syncthreads();

    if (tid < 32) {
        float s = 0.f;
        #pragma unroll 8
        for (int p2 = 0; p2 < 64; p2++) s += s_red[tid * 65 + p2];
        float part = wc[cg * 32 + tid] * s * (1.0f / 64.0f);
        #pragma unroll
        for (int off = 16; off; off >>= 1)
            part += __shfl_down_sync(0xffffffffu, part, off);
        if (tid == 0) atomicAdd(&out[b], part);
    }
}

extern "C" void kernel_launch(void* const* d_in, const int* in_sizes, int n_in,
                              void* d_out, int out_size) {
    const float* x  = (const float*)d_in[0];
    const float* w1 = (const float*)d_in[1];
    const float* b1 = (const float*)d_in[2];
    const float* w2 = (const float*)d_in[3];
    const float* b2 = (const float*)d_in[4];
    const float* w3 = (const float*)d_in[5];
    const float* b3 = (const float*)d_in[6];
    const float* wc = (const float*)d_in[7];
    const float* bc = (const float*)d_in[8];
    float* out = (float*)d_out;

    const size_t sm12 = 38592 * sizeof(float);                  // 150.75 KB
    const size_t sm3  = (52480 + 2080) * sizeof(float);         // 218 KB

    cudaFuncSetAttribute(k12_conv, cudaFuncAttributeMaxDynamicSharedMemorySize, (int)sm12);
    cudaFuncSetAttribute(k3_conv,  cudaFuncAttributeMaxDynamicSharedMemorySize, (int)sm3);

    k12_conv<<<dim3(32, 4), 512, sm12>>>(x, w1, b1, w2, b2, bc, out);
    k3_conv<<<dim3(32, 4), 512, sm3>>>(w3, b3, wc, out);
}